// round 10
// baseline (speedup 1.0000x reference)
#include <cuda_runtime.h>
#include <cuda_bf16.h>
#include <cuda_fp16.h>
#include <math.h>
#include <stdint.h>

#define NROWS 32768
#define HD    1024
#define DZ    5e-4f
#define EPS0  2.56e-4f   // 1024*DZ^2

// ---------------------------------------------------------------------------
// Scratch
// ---------------------------------------------------------------------------
__device__ int8_t g_xa1[(size_t)NROWS * HD];
__device__ int8_t g_xa2[(size_t)NROWS * HD];
__device__ int8_t g_ha1[(size_t)NROWS * HD];
__device__ int8_t g_ha2[(size_t)NROWS * HD];
__device__ int8_t g_wb1[2][(size_t)HD * HD];
__device__ int8_t g_wb2[2][(size_t)HD * HD];
__device__ __half g_xhi[(size_t)NROWS * HD];
__device__ __half g_xlo[(size_t)NROWS * HD];
__device__ __half g_w12h[2][(size_t)HD * HD];
__device__ __half g_w12l[2][(size_t)HD * HD];
__device__ __nv_bfloat16 g_zqh[(size_t)NROWS * HD];
__device__ __nv_bfloat16 g_h3b[(size_t)NROWS * HD];
__device__ __nv_bfloat16 g_w34[2][(size_t)HD * HD];
__device__ __half g_resh[(size_t)NROWS * HD];
__device__ __half g_resl[(size_t)NROWS * HD];
__device__ float  g_resz[(size_t)NROWS * HD];
__device__ int    g_list[NROWS];
__device__ int    g_count;
__device__ float  g_rowsum[HD];
__device__ float  g_rowsq[HD];

// ---------------------------------------------------------------------------
// PTX helpers
// ---------------------------------------------------------------------------
__device__ __forceinline__ uint32_t smem_to_u32(const void* p) {
    uint32_t a;
    asm("{ .reg .u64 t; cvta.to.shared.u64 t, %1; cvt.u32.u64 %0, t; }" : "=r"(a) : "l"(p));
    return a;
}
#define CP_ASYNC16(dst, src) \
    asm volatile("cp.async.cg.shared.global [%0], [%1], 16;" :: "r"(dst), "l"(src))
#define CP_COMMIT() asm volatile("cp.async.commit_group;" ::: "memory")
#define CP_WAIT2()  asm volatile("cp.async.wait_group 2;" ::: "memory")
#define CP_WAIT1()  asm volatile("cp.async.wait_group 1;" ::: "memory")
#define CP_WAIT0()  asm volatile("cp.async.wait_group 0;" ::: "memory")

#define LDSM4(r0, r1, r2, r3, addr) \
    asm volatile("ldmatrix.sync.aligned.m8n8.x4.shared.b16 {%0,%1,%2,%3}, [%4];" \
        : "=r"(r0), "=r"(r1), "=r"(r2), "=r"(r3) : "r"(addr))

#define MMAB(d, a, b) \
    asm volatile("mma.sync.aligned.m16n8k16.row.col.f32.bf16.bf16.f32 " \
        "{%0,%1,%2,%3}, {%4,%5,%6,%7}, {%8,%9}, {%0,%1,%2,%3};" \
        : "+f"((d)[0]), "+f"((d)[1]), "+f"((d)[2]), "+f"((d)[3]) \
        : "r"((a)[0]), "r"((a)[1]), "r"((a)[2]), "r"((a)[3]), "r"((b)[0]), "r"((b)[1]))

#define MMAH(d, a, b) \
    asm volatile("mma.sync.aligned.m16n8k16.row.col.f32.f16.f16.f32 " \
        "{%0,%1,%2,%3}, {%4,%5,%6,%7}, {%8,%9}, {%0,%1,%2,%3};" \
        : "+f"((d)[0]), "+f"((d)[1]), "+f"((d)[2]), "+f"((d)[3]) \
        : "r"((a)[0]), "r"((a)[1]), "r"((a)[2]), "r"((a)[3]), "r"((b)[0]), "r"((b)[1]))

#define MMAI(d, a, b) \
    asm volatile("mma.sync.aligned.m16n8k32.row.col.s32.s8.s8.s32 " \
        "{%0,%1,%2,%3}, {%4,%5,%6,%7}, {%8,%9}, {%0,%1,%2,%3};" \
        : "+r"((d)[0]), "+r"((d)[1]), "+r"((d)[2]), "+r"((d)[3]) \
        : "r"((a)[0]), "r"((a)[1]), "r"((a)[2]), "r"((a)[3]), "r"((b)[0]), "r"((b)[1]))

__device__ __forceinline__ void split1h(float v, __half& h, __half& l) {
    h = __float2half_rn(v);
    l = __float2half_rn(v - __half2float(h));
}
__device__ __forceinline__ void q2(float v, float inv1, float s1, float inv2,
                                   int lo1, int hi1, int8_t& c1, int8_t& c2) {
    int a = max(lo1, min(hi1, (int)rintf(v * inv1)));
    float r = v - (float)a * s1;
    int b = max(-64, min(64, (int)rintf(r * inv2)));
    c1 = (int8_t)a; c2 = (int8_t)b;
}

// ---------------------------------------------------------------------------
// Prep kernels
// ---------------------------------------------------------------------------
__global__ void zero_cnt_kernel() { if (threadIdx.x == 0) g_count = 0; }

// x -> int8 chunks (sx=1/127) + fp16 hi/lo (for rescue)
__global__ __launch_bounds__(256)
void qx_kernel(const float4* __restrict__ x, char4* __restrict__ a1,
               char4* __restrict__ a2, __half2* __restrict__ hi,
               __half2* __restrict__ lo)
{
    size_t i = (size_t)blockIdx.x * 256 + threadIdx.x;
    float4 v = x[i];
    char4 c1, c2;
    q2(v.x, 127.f, 1.f/127.f, 16256.f, 0, 127, c1.x, c2.x);
    q2(v.y, 127.f, 1.f/127.f, 16256.f, 0, 127, c1.y, c2.y);
    q2(v.z, 127.f, 1.f/127.f, 16256.f, 0, 127, c1.z, c2.z);
    q2(v.w, 127.f, 1.f/127.f, 16256.f, 0, 127, c1.w, c2.w);
    a1[i] = c1; a2[i] = c2;
    __half h0,l0,h1,l1,h2,l2,h3,l3;
    split1h(v.x,h0,l0); split1h(v.y,h1,l1); split1h(v.z,h2,l2); split1h(v.w,h3,l3);
    __half2 a,b;
    a.x=h0; a.y=h1; b.x=h2; b.y=h3; hi[2*i]=a; hi[2*i+1]=b;
    a.x=l0; a.y=l1; b.x=l2; b.y=l3; lo[2*i]=a; lo[2*i+1]=b;
}

// W[K,N] -> Wt[N,K]: int8 chunks (sw=0.15/127) + fp16 hi/lo
__global__ __launch_bounds__(1024)
void qw_kernel(const float* __restrict__ W, int8_t* __restrict__ b1c,
               int8_t* __restrict__ b2c, __half* __restrict__ hi,
               __half* __restrict__ lo)
{
    __shared__ float s[32][33];
    int n0 = blockIdx.x * 32, k0 = blockIdx.y * 32;
    s[threadIdx.y][threadIdx.x] = W[(size_t)(k0 + threadIdx.y) * HD + n0 + threadIdx.x];
    __syncthreads();
    float v = s[threadIdx.x][threadIdx.y];
    int n = n0 + threadIdx.y, k = k0 + threadIdx.x;
    const float sw = 0.15f / 127.f;
    int8_t c1, c2;
    q2(v, 1.f/sw, sw, 128.f/sw, -127, 127, c1, c2);
    b1c[(size_t)n * HD + k] = c1;
    b2c[(size_t)n * HD + k] = c2;
    __half h, l; split1h(v, h, l);
    hi[(size_t)n * HD + k] = h;
    lo[(size_t)n * HD + k] = l;
}

__global__ __launch_bounds__(1024)
void wt_b(const float* __restrict__ W, __nv_bfloat16* __restrict__ hi)
{
    __shared__ float s[32][33];
    int n0 = blockIdx.x * 32, k0 = blockIdx.y * 32;
    s[threadIdx.y][threadIdx.x] = W[(size_t)(k0 + threadIdx.y) * HD + n0 + threadIdx.x];
    __syncthreads();
    float v = s[threadIdx.x][threadIdx.y];
    hi[(size_t)(n0 + threadIdx.y) * HD + k0 + threadIdx.x] = __float2bfloat16(v);
}

__global__ __launch_bounds__(256)
void cb_stats_kernel(const float* __restrict__ cb, float* __restrict__ rowsum,
                     float* __restrict__ rowsq)
{
    const int i = blockIdx.x, tid = threadIdx.x;
    const float* row = cb + (size_t)i * HD;
    float s = 0.f, q = 0.f;
    for (int j = tid; j < HD; j += 256) { float v = row[j]; s += v; q = fmaf(v, v, q); }
    __shared__ float ss[256], qq[256];
    ss[tid] = s; qq[tid] = q;
    __syncthreads();
    for (int off = 128; off > 0; off >>= 1) {
        if (tid < off) { ss[tid] += ss[tid+off]; qq[tid] += qq[tid+off]; }
        __syncthreads();
    }
    if (tid == 0) { rowsum[i] = ss[0]; rowsq[i] = qq[0]; }
}

// ---------------------------------------------------------------------------
// int8 3-term GEMM: C = relu((A1 + A2/128) @ (B1 + B2/128)^T * scale + bias)
// CTA 128x128, 256 thr, 8 warps (warp 64x32), KC=128 int8 (=128B rows).
// MODE 0: fp32 out; MODE 1: int8 2-chunk out (h range [0,4], s1=4/127).
// ---------------------------------------------------------------------------
#define I_KC  128
#define I_NKI (HD / I_KC)   // 8
#define I_A1o 0
#define I_A2o 16384
#define I_B1o 32768
#define I_B2o 49152
#define I_STG 65536
#define I_SMEM (2 * I_STG)  // 131072

__device__ __forceinline__ void load_i(
    uint32_t sdst, const int8_t* __restrict__ A1, const int8_t* __restrict__ A2,
    const int8_t* __restrict__ B1, const int8_t* __restrict__ B2,
    int mbase, int nbase, int c, int tid)
{
    const int kel = c * I_KC;
    #pragma unroll
    for (int i = 0; i < 4; ++i) {
        int id = tid + i * 256;
        int row = id >> 3, u = id & 7;
        uint32_t so = row * 128 + ((u ^ (row & 7)) << 4);
        CP_ASYNC16(sdst + I_A1o + so, (const char*)(A1 + (size_t)(mbase + row) * HD + kel + u * 16));
        CP_ASYNC16(sdst + I_A2o + so, (const char*)(A2 + (size_t)(mbase + row) * HD + kel + u * 16));
        CP_ASYNC16(sdst + I_B1o + so, (const char*)(B1 + (size_t)(nbase + row) * HD + kel + u * 16));
        CP_ASYNC16(sdst + I_B2o + so, (const char*)(B2 + (size_t)(nbase + row) * HD + kel + u * 16));
    }
}

template<int MODE>
__global__ __launch_bounds__(256, 1)
void gemm_i3(const int8_t* __restrict__ A1, const int8_t* __restrict__ A2,
             const int8_t* __restrict__ B1, const int8_t* __restrict__ B2,
             const float* __restrict__ bias, float scale,
             float* __restrict__ Cf, int8_t* __restrict__ C1, int8_t* __restrict__ C2)
{
    extern __shared__ char smem[];
    const uint32_t sb = smem_to_u32(smem);
    const int tid = threadIdx.x, wid = tid >> 5, lane = tid & 31;
    const int wm = wid & 1, wn = wid >> 1;     // m: 2x64, n: 4x32
    const int mbase = blockIdx.y * 128, nbase = blockIdx.x * 128;

    int acc1[4][4][4], acc23[4][4][4];
    #pragma unroll
    for (int i = 0; i < 4; i++)
        #pragma unroll
        for (int j = 0; j < 4; j++)
            #pragma unroll
            for (int k = 0; k < 4; k++) { acc1[i][j][k] = 0; acc23[i][j][k] = 0; }

    const int a_row_l = lane & 15, a_half = lane >> 4;
    const int b_n_l = (lane & 7) + ((lane >> 4) << 3), b_half = (lane >> 3) & 1;

    load_i(sb, A1, A2, B1, B2, mbase, nbase, 0, tid);
    CP_COMMIT();

    for (int c = 0; c < I_NKI; ++c) {
        if (c + 1 < I_NKI) {
            load_i(sb + ((c + 1) & 1) * I_STG, A1, A2, B1, B2, mbase, nbase, c + 1, tid);
            CP_COMMIT(); CP_WAIT1();
        } else CP_WAIT0();
        __syncthreads();

        const uint32_t st = sb + (c & 1) * I_STG;
        #pragma unroll
        for (int ks = 0; ks < 4; ++ks) {
            uint32_t a[4][4], br1[4][2], br2[4][2];
            #pragma unroll
            for (int i = 0; i < 4; ++i) {
                int row = wm * 64 + i * 16 + a_row_l, u = ks * 2 + a_half;
                LDSM4(a[i][0], a[i][1], a[i][2], a[i][3],
                      st + I_A1o + row * 128 + ((u ^ (row & 7)) << 4));
            }
            #pragma unroll
            for (int jj = 0; jj < 2; ++jj) {
                int n = wn * 32 + jj * 16 + b_n_l, u = ks * 2 + b_half;
                LDSM4(br1[jj*2][0], br1[jj*2][1], br1[jj*2+1][0], br1[jj*2+1][1],
                      st + I_B1o + n * 128 + ((u ^ (n & 7)) << 4));
                LDSM4(br2[jj*2][0], br2[jj*2][1], br2[jj*2+1][0], br2[jj*2+1][1],
                      st + I_B2o + n * 128 + ((u ^ (n & 7)) << 4));
            }
            #pragma unroll
            for (int i = 0; i < 4; ++i)
                #pragma unroll
                for (int j = 0; j < 4; ++j) {
                    MMAI(acc1[i][j],  a[i], br1[j]);
                    MMAI(acc23[i][j], a[i], br2[j]);
                }
            #pragma unroll
            for (int i = 0; i < 4; ++i) {
                int row = wm * 64 + i * 16 + a_row_l, u = ks * 2 + a_half;
                LDSM4(a[i][0], a[i][1], a[i][2], a[i][3],
                      st + I_A2o + row * 128 + ((u ^ (row & 7)) << 4));
            }
            #pragma unroll
            for (int i = 0; i < 4; ++i)
                #pragma unroll
                for (int j = 0; j < 4; ++j)
                    MMAI(acc23[i][j], a[i], br1[j]);
        }
        __syncthreads();
    }

    #pragma unroll
    for (int j = 0; j < 4; ++j) {
        const int col = nbase + wn * 32 + j * 8 + (lane & 3) * 2;
        const float2 bj = *reinterpret_cast<const float2*>(bias + col);
        #pragma unroll
        for (int i = 0; i < 4; ++i) {
            const int r0 = mbase + wm * 64 + i * 16 + (lane >> 2);
            const int r1 = r0 + 8;
            float v0 = fmaxf(fmaf((float)acc23[i][j][0], 0.0078125f, (float)acc1[i][j][0]) * scale + bj.x, 0.f);
            float v1 = fmaxf(fmaf((float)acc23[i][j][1], 0.0078125f, (float)acc1[i][j][1]) * scale + bj.y, 0.f);
            float v2 = fmaxf(fmaf((float)acc23[i][j][2], 0.0078125f, (float)acc1[i][j][2]) * scale + bj.x, 0.f);
            float v3 = fmaxf(fmaf((float)acc23[i][j][3], 0.0078125f, (float)acc1[i][j][3]) * scale + bj.y, 0.f);
            if (MODE == 0) {
                float2 p0 = {v0, v1}, p1 = {v2, v3};
                *reinterpret_cast<float2*>(Cf + (size_t)r0 * HD + col) = p0;
                *reinterpret_cast<float2*>(Cf + (size_t)r1 * HD + col) = p1;
            } else {
                const float s1 = 4.f / 127.f;
                char2 q1a, q1b, q2a, q2b;
                q2(v0, 31.75f, s1, 4064.f, 0, 127, q1a.x, q2a.x);
                q2(v1, 31.75f, s1, 4064.f, 0, 127, q1a.y, q2a.y);
                q2(v2, 31.75f, s1, 4064.f, 0, 127, q1b.x, q2b.x);
                q2(v3, 31.75f, s1, 4064.f, 0, 127, q1b.y, q2b.y);
                *reinterpret_cast<char2*>(C1 + (size_t)r0 * HD + col) = q1a;
                *reinterpret_cast<char2*>(C2 + (size_t)r0 * HD + col) = q2a;
                *reinterpret_cast<char2*>(C1 + (size_t)r1 * HD + col) = q1b;
                *reinterpret_cast<char2*>(C2 + (size_t)r1 * HD + col) = q2b;
            }
        }
    }
}

// ---------------------------------------------------------------------------
// VQ with error-certified flagging + gather
// ---------------------------------------------------------------------------
__global__ __launch_bounds__(256)
void vq2e_kernel(const float* __restrict__ ze, const float* __restrict__ cb,
                 const float* __restrict__ rowsum, const float* __restrict__ rowsq,
                 float* __restrict__ zq, __nv_bfloat16* __restrict__ zqh,
                 int* __restrict__ list, int* __restrict__ cnt)
{
    const int n = blockIdx.x, tid = threadIdx.x;
    const float* z = ze + (size_t)n * HD;
    float d1 = INFINITY, d2 = INFINITY, e1 = 0.f, e2 = 0.f;
    int i1 = 0x7fffffff;
    #pragma unroll
    for (int j = 0; j < 4; j++) {
        int i = tid + j * 256;
        float zv = z[i];
        float rs = rowsum[i];
        float d = fmaf(1024.0f * zv, zv, fmaf(-2.0f * zv, rs, rowsq[i]));
        float ep = DZ * fmaf(2048.f, zv, 2.f * fabsf(rs)) + EPS0;
        if (d < d1 || (d == d1 && i < i1)) { d2 = d1; e2 = e1; d1 = d; i1 = i; e1 = ep; }
        else if (d < d2) { d2 = d; e2 = ep; }
    }
    __shared__ float sd1[256], sd2[256], se1[256], se2[256];
    __shared__ int si1[256];
    sd1[tid] = d1; sd2[tid] = d2; se1[tid] = e1; se2[tid] = e2; si1[tid] = i1;
    __syncthreads();
    for (int off = 128; off > 0; off >>= 1) {
        if (tid < off) {
            float od1 = sd1[tid+off], od2 = sd2[tid+off];
            float oe1 = se1[tid+off], oe2 = se2[tid+off];
            int   oi1 = si1[tid+off];
            float md1 = sd1[tid], md2 = sd2[tid];
            float me1 = se1[tid];
            int   mi1 = si1[tid];
            if (od1 < md1 || (od1 == md1 && oi1 < mi1)) {
                if (md1 < od2) { sd2[tid] = md1; se2[tid] = me1; }
                else           { sd2[tid] = od2; se2[tid] = oe2; }
                sd1[tid] = od1; si1[tid] = oi1; se1[tid] = oe1;
            } else {
                if (od1 < md2) { sd2[tid] = od1; se2[tid] = oe1; }
            }
        }
        __syncthreads();
    }
    const int idx = si1[0];
    if (tid == 0 && (sd2[0] - sd1[0]) < (se1[0] + se2[0])) {
        int p = atomicAdd(cnt, 1);
        list[p] = n;
    }
    float4 v = reinterpret_cast<const float4*>(cb + (size_t)idx * HD)[tid];
    reinterpret_cast<float4*>(zq + (size_t)n * HD)[tid] = v;
    __nv_bfloat162 a, b;
    a.x = __float2bfloat16(v.x); a.y = __float2bfloat16(v.y);
    b.x = __float2bfloat16(v.z); b.y = __float2bfloat16(v.w);
    __nv_bfloat162* ph = reinterpret_cast<__nv_bfloat162*>(zqh + (size_t)n * HD);
    ph[2*tid] = a; ph[2*tid+1] = b;
}

// ---------------------------------------------------------------------------
// Rescue fix-up (verbatim R9)
// ---------------------------------------------------------------------------
__global__ __launch_bounds__(256)
void rescue_dist(const float* __restrict__ resz, const float* __restrict__ cb,
                 const float* __restrict__ rowsum, const float* __restrict__ rowsq,
                 float* __restrict__ zq, float* __restrict__ ze,
                 __nv_bfloat16* __restrict__ zqh,
                 const int* __restrict__ list, const int* __restrict__ cntp)
{
    const int cnt = *cntp;
    const int b = blockIdx.x;
    if (b >= cnt) return;
    const int n = list[b];
    const int tid = threadIdx.x;
    const float* z = resz + (size_t)b * HD;

    float best = INFINITY; int bidx = 0x7fffffff;
    #pragma unroll
    for (int j = 0; j < 4; j++) {
        int i = tid + j * 256;
        float zv = z[i];
        float d = fmaf(1024.0f * zv, zv, fmaf(-2.0f * zv, rowsum[i], rowsq[i]));
        if (d < best || (d == best && i < bidx)) { best = d; bidx = i; }
    }
    __shared__ float sd[256]; __shared__ int si[256];
    sd[tid] = best; si[tid] = bidx;
    __syncthreads();
    for (int off = 128; off > 0; off >>= 1) {
        if (tid < off) {
            float dd = sd[tid+off]; int ii = si[tid+off];
            if (dd < sd[tid] || (dd == sd[tid] && ii < si[tid])) { sd[tid]=dd; si[tid]=ii; }
        }
        __syncthreads();
    }
    const int idx = si[0];
    float4 zv4 = reinterpret_cast<const float4*>(z)[tid];
    reinterpret_cast<float4*>(ze + (size_t)n * HD)[tid] = zv4;
    float4 v = reinterpret_cast<const float4*>(cb + (size_t)idx * HD)[tid];
    reinterpret_cast<float4*>(zq + (size_t)n * HD)[tid] = v;
    __nv_bfloat162 a, bb;
    a.x = __float2bfloat16(v.x); a.y = __float2bfloat16(v.y);
    bb.x = __float2bfloat16(v.z); bb.y = __float2bfloat16(v.w);
    __nv_bfloat162* ph = reinterpret_cast<__nv_bfloat162*>(zqh + (size_t)n * HD);
    ph[2*tid] = a; ph[2*tid+1] = bb;
}

// ---------------------------------------------------------------------------
// fp16/bf16 GEMM geometry (verbatim R9): CTA 256x128, 256 thr, warp 64x64
// ---------------------------------------------------------------------------
#define BM 256
#define BN 128
#define KC 64
#define NKI (HD / KC)
#define THREADS 256

// ===== 3-term fp16 rescue GEMM (verbatim R9) =====
#define R_AH 0
#define R_AL 32768
#define R_BH 65536
#define R_BL 81920
#define R_STG 98304
#define R_SMEM (2 * R_STG)

template<int IND>
__device__ __forceinline__ void load_r(
    uint32_t sdst, const __half* __restrict__ Ahi, const __half* __restrict__ Alo,
    const __half* __restrict__ Bh, const __half* __restrict__ Bl,
    int mbase, int nbase, int c, int tid, const int* __restrict__ list, int cnt)
{
    const int kel = c * KC;
    #pragma unroll
    for (int i = 0; i < 8; ++i) {
        int id = tid + i * THREADS;
        int row = id >> 3, u = id & 7;
        int srow = mbase + row;
        if (IND) srow = __ldg(list + min(srow, cnt - 1));
        uint32_t so = row * 128 + ((u ^ (row & 7)) << 4);
        CP_ASYNC16(sdst + R_AH + so, (const char*)(Ahi + (size_t)srow * HD + kel + u * 8));
        CP_ASYNC16(sdst + R_AL + so, (const char*)(Alo + (size_t)srow * HD + kel + u * 8));
    }
    #pragma unroll
    for (int i = 0; i < 4; ++i) {
        int id = tid + i * THREADS;
        int row = id >> 3, u = id & 7;
        uint32_t so = row * 128 + ((u ^ (row & 7)) << 4);
        CP_ASYNC16(sdst + R_BH + so, (const char*)(Bh + (size_t)(nbase + row) * HD + kel + u * 8));
        CP_ASYNC16(sdst + R_BL + so, (const char*)(Bl + (size_t)(nbase + row) * HD + kel + u * 8));
    }
}

template<int MODE, int IND>
__global__ __launch_bounds__(THREADS, 1)
void gemm_h3(const __half* __restrict__ Ahi, const __half* __restrict__ Alo,
             const __half* __restrict__ Bh, const __half* __restrict__ Bl,
             const float* __restrict__ bias,
             float* __restrict__ Cf, __half* __restrict__ Chi, __half* __restrict__ Clo,
             const int* __restrict__ list, const int* __restrict__ cntp)
{
    const int cnt = __ldg(cntp);
    const int mbase = blockIdx.y * BM;
    if (mbase >= cnt) return;
    extern __shared__ char smem[];
    const uint32_t sb = smem_to_u32(smem);
    const int tid = threadIdx.x, wid = tid >> 5, lane = tid & 31;
    const int wm = wid & 3, wn = wid >> 2;
    const int nbase = blockIdx.x * BN;

    float acc[4][8][4];
    #pragma unroll
    for (int i = 0; i < 4; i++)
        #pragma unroll
        for (int j = 0; j < 8; j++)
            #pragma unroll
            for (int k = 0; k < 4; k++) acc[i][j][k] = 0.f;

    const int a_row_l = lane & 15, a_half = lane >> 4;
    const int b_n_l = (lane & 7) + ((lane >> 4) << 3), b_half = (lane >> 3) & 1;

    load_r<IND>(sb, Ahi, Alo, Bh, Bl, mbase, nbase, 0, tid, list, cnt);
    CP_COMMIT();

    for (int c = 0; c < NKI; ++c) {
        if (c + 1 < NKI) {
            load_r<IND>(sb + ((c + 1) & 1) * R_STG, Ahi, Alo, Bh, Bl,
                        mbase, nbase, c + 1, tid, list, cnt);
            CP_COMMIT(); CP_WAIT1();
        } else CP_WAIT0();
        __syncthreads();

        const uint32_t st = sb + (c & 1) * R_STG;
        #pragma unroll
        for (int ks = 0; ks < 4; ++ks) {
            uint32_t ah[4][4], bh[8][2], bl[8][2];
            #pragma unroll
            for (int i = 0; i < 4; ++i) {
                int row = wm * 64 + i * 16 + a_row_l, u = ks * 2 + a_half;
                LDSM4(ah[i][0], ah[i][1], ah[i][2], ah[i][3],
                      st + R_AH + row * 128 + ((u ^ (row & 7)) << 4));
            }
            #pragma unroll
            for (int jj = 0; jj < 4; ++jj) {
                int n = wn * 64 + jj * 16 + b_n_l, u = ks * 2 + b_half;
                LDSM4(bh[jj*2][0], bh[jj*2][1], bh[jj*2+1][0], bh[jj*2+1][1],
                      st + R_BH + n * 128 + ((u ^ (n & 7)) << 4));
                LDSM4(bl[jj*2][0], bl[jj*2][1], bl[jj*2+1][0], bl[jj*2+1][1],
                      st + R_BL + n * 128 + ((u ^ (n & 7)) << 4));
            }
            #pragma unroll
            for (int i = 0; i < 4; ++i)
                #pragma unroll
                for (int j = 0; j < 8; ++j) {
                    MMAH(acc[i][j], ah[i], bh[j]);
                    MMAH(acc[i][j], ah[i], bl[j]);
                }
            #pragma unroll
            for (int i = 0; i < 4; ++i) {
                int row = wm * 64 + i * 16 + a_row_l, u = ks * 2 + a_half;
                LDSM4(ah[i][0], ah[i][1], ah[i][2], ah[i][3],
                      st + R_AL + row * 128 + ((u ^ (row & 7)) << 4));
            }
            #pragma unroll
            for (int i = 0; i < 4; ++i)
                #pragma unroll
                for (int j = 0; j < 8; ++j)
                    MMAH(acc[i][j], ah[i], bh[j]);
        }
        __syncthreads();
    }

    #pragma unroll
    for (int j = 0; j < 8; ++j) {
        const int col = nbase + wn * 64 + j * 8 + (lane & 3) * 2;
        const float2 bj = *reinterpret_cast<const float2*>(bias + col);
        #pragma unroll
        for (int i = 0; i < 4; ++i) {
            const int r0 = mbase + wm * 64 + i * 16 + (lane >> 2);
            const int r1 = r0 + 8;
            float v0 = fmaxf(acc[i][j][0] + bj.x, 0.f);
            float v1 = fmaxf(acc[i][j][1] + bj.y, 0.f);
            float v2 = fmaxf(acc[i][j][2] + bj.x, 0.f);
            float v3 = fmaxf(acc[i][j][3] + bj.y, 0.f);
            if (MODE == 0) {
                float2 p0 = {v0, v1}, p1 = {v2, v3};
                *reinterpret_cast<float2*>(Cf + (size_t)r0 * HD + col) = p0;
                *reinterpret_cast<float2*>(Cf + (size_t)r1 * HD + col) = p1;
            } else {
                __half h0,l0,h1,l1,h2,l2,h3,l3;
                split1h(v0,h0,l0); split1h(v1,h1,l1); split1h(v2,h2,l2); split1h(v3,h3,l3);
                __half2 hh0; hh0.x=h0; hh0.y=h1;
                __half2 ll0; ll0.x=l0; ll0.y=l1;
                __half2 hh1; hh1.x=h2; hh1.y=h3;
                __half2 ll1; ll1.x=l2; ll1.y=l3;
                *reinterpret_cast<__half2*>(Chi + (size_t)r0 * HD + col) = hh0;
                *reinterpret_cast<__half2*>(Clo + (size_t)r0 * HD + col) = ll0;
                *reinterpret_cast<__half2*>(Chi + (size_t)r1 * HD + col) = hh1;
                *reinterpret_cast<__half2*>(Clo + (size_t)r1 * HD + col) = ll1;
            }
        }
    }
}

// ===== 1-term bf16 decoder (verbatim R9) =====
#define D_A 0
#define D_B 32768
#define D_STG 49152
#define D_SMEM (3 * D_STG)

__device__ __forceinline__ void load_d(
    uint32_t sdst, const __nv_bfloat16* __restrict__ A, const __nv_bfloat16* __restrict__ B,
    int mbase, int nbase, int c, int tid)
{
    const int kel = c * KC;
    #pragma unroll
    for (int i = 0; i < 8; ++i) {
        int id = tid + i * THREADS;
        int row = id >> 3, u = id & 7;
        CP_ASYNC16(sdst + D_A + row * 128 + ((u ^ (row & 7)) << 4),
                   (const char*)(A + (size_t)(mbase + row) * HD + kel + u * 8));
    }
    #pragma unroll
    for (int i = 0; i < 4; ++i) {
        int id = tid + i * THREADS;
        int row = id >> 3, u = id & 7;
        CP_ASYNC16(sdst + D_B + row * 128 + ((u ^ (row & 7)) << 4),
                   (const char*)(B + (size_t)(nbase + row) * HD + kel + u * 8));
    }
}

template<int EPI, int MODE>
__global__ __launch_bounds__(THREADS, 1)
void gemm_b1(const __nv_bfloat16* __restrict__ A, const __nv_bfloat16* __restrict__ B,
             const float* __restrict__ bias,
             float* __restrict__ Cf, __nv_bfloat16* __restrict__ Chi)
{
    extern __shared__ char smem[];
    const uint32_t sb = smem_to_u32(smem);
    const int tid = threadIdx.x, wid = tid >> 5, lane = tid & 31;
    const int wm = wid & 3, wn = wid >> 2;
    const int mbase = blockIdx.y * BM, nbase = blockIdx.x * BN;

    float acc[4][8][4];
    #pragma unroll
    for (int i = 0; i < 4; i++)
        #pragma unroll
        for (int j = 0; j < 8; j++)
            #pragma unroll
            for (int k = 0; k < 4; k++) acc[i][j][k] = 0.f;

    const int a_row_l = lane & 15, a_half = lane >> 4;
    const int b_n_l = (lane & 7) + ((lane >> 4) << 3), b_half = (lane >> 3) & 1;

    load_d(sb + 0 * D_STG, A, B, mbase, nbase, 0, tid);
    CP_COMMIT();
    load_d(sb + 1 * D_STG, A, B, mbase, nbase, 1, tid);
    CP_COMMIT();

    int buf = 0;
    for (int c = 0; c < NKI; ++c) {
        if (c + 2 < NKI) {
            int b2 = buf + 2; if (b2 >= 3) b2 -= 3;
            load_d(sb + b2 * D_STG, A, B, mbase, nbase, c + 2, tid);
            CP_COMMIT(); CP_WAIT2();
        } else if (c + 1 < NKI) CP_WAIT1();
        else CP_WAIT0();
        __syncthreads();

        const uint32_t st = sb + buf * D_STG;
        #pragma unroll
        for (int ks = 0; ks < 4; ++ks) {
            uint32_t ah[4][4], bh[8][2];
            #pragma unroll
            for (int i = 0; i < 4; ++i) {
                int row = wm * 64 + i * 16 + a_row_l, u = ks * 2 + a_half;
                LDSM4(ah[i][0], ah[i][1], ah[i][2], ah[i][3],
                      st + D_A + row * 128 + ((u ^ (row & 7)) << 4));
            }
            #pragma unroll
            for (int jj = 0; jj < 4; ++jj) {
                int n = wn * 64 + jj * 16 + b_n_l, u = ks * 2 + b_half;
                LDSM4(bh[jj*2][0], bh[jj*2][1], bh[jj*2+1][0], bh[jj*2+1][1],
                      st + D_B + n * 128 + ((u ^ (n & 7)) << 4));
            }
            #pragma unroll
            for (int i = 0; i < 4; ++i)
                #pragma unroll
                for (int j = 0; j < 8; ++j)
                    MMAB(acc[i][j], ah[i], bh[j]);
        }
        __syncthreads();
        buf = buf + 1; if (buf == 3) buf = 0;
    }

    #pragma unroll
    for (int j = 0; j < 8; ++j) {
        const int col = nbase + wn * 64 + j * 8 + (lane & 3) * 2;
        const float2 bj = *reinterpret_cast<const float2*>(bias + col);
        #pragma unroll
        for (int i = 0; i < 4; ++i) {
            const int r0 = mbase + wm * 64 + i * 16 + (lane >> 2);
            const int r1 = r0 + 8;
            float v0 = acc[i][j][0] + bj.x;
            float v1 = acc[i][j][1] + bj.y;
            float v2 = acc[i][j][2] + bj.x;
            float v3 = acc[i][j][3] + bj.y;
            if (EPI == 0) {
                v0 = fmaxf(v0, 0.f); v1 = fmaxf(v1, 0.f);
                v2 = fmaxf(v2, 0.f); v3 = fmaxf(v3, 0.f);
            } else {
                v0 = 1.f / (1.f + expf(-v0)); v1 = 1.f / (1.f + expf(-v1));
                v2 = 1.f / (1.f + expf(-v2)); v3 = 1.f / (1.f + expf(-v3));
            }
            if (MODE == 0) {
                float2 p0 = {v0, v1}, p1 = {v2, v3};
                *reinterpret_cast<float2*>(Cf + (size_t)r0 * HD + col) = p0;
                *reinterpret_cast<float2*>(Cf + (size_t)r1 * HD + col) = p1;
            } else {
                __nv_bfloat162 hh0, hh1;
                hh0.x = __float2bfloat16(v0); hh0.y = __float2bfloat16(v1);
                hh1.x = __float2bfloat16(v2); hh1.y = __float2bfloat16(v3);
                *reinterpret_cast<__nv_bfloat162*>(Chi + (size_t)r0 * HD + col) = hh0;
                *reinterpret_cast<__nv_bfloat162*>(Chi + (size_t)r1 * HD + col) = hh1;
            }
        }
    }
}

// ---------------------------------------------------------------------------
// Launch
// ---------------------------------------------------------------------------
extern "C" void kernel_launch(void* const* d_in, const int* in_sizes, int n_in,
                              void* d_out, int out_size)
{
    const float* x  = (const float*)d_in[0];
    const float* W1 = (const float*)d_in[1];
    const float* b1 = (const float*)d_in[2];
    const float* W2 = (const float*)d_in[3];
    const float* b2 = (const float*)d_in[4];
    const float* cb = (const float*)d_in[5];
    const float* W3 = (const float*)d_in[6];
    const float* b3 = (const float*)d_in[7];
    const float* W4 = (const float*)d_in[8];
    const float* b4 = (const float*)d_in[9];

    float* out = (float*)d_out;
    float* x_recon = out;
    float* z_e = out + (size_t)NROWS * HD;
    float* z_q = z_e + (size_t)NROWS * HD;

    int8_t *xa1, *xa2, *ha1, *ha2, *wb1, *wb2;
    __half *xhi, *xlo, *w12h, *w12l, *resh, *resl;
    __nv_bfloat16 *zqh, *h3b, *w34;
    float *rs, *rq, *resz;
    int *lst, *cnt;
    cudaGetSymbolAddress((void**)&xa1,  g_xa1);
    cudaGetSymbolAddress((void**)&xa2,  g_xa2);
    cudaGetSymbolAddress((void**)&ha1,  g_ha1);
    cudaGetSymbolAddress((void**)&ha2,  g_ha2);
    cudaGetSymbolAddress((void**)&wb1,  g_wb1);
    cudaGetSymbolAddress((void**)&wb2,  g_wb2);
    cudaGetSymbolAddress((void**)&xhi,  g_xhi);
    cudaGetSymbolAddress((void**)&xlo,  g_xlo);
    cudaGetSymbolAddress((void**)&w12h, g_w12h);
    cudaGetSymbolAddress((void**)&w12l, g_w12l);
    cudaGetSymbolAddress((void**)&zqh,  g_zqh);
    cudaGetSymbolAddress((void**)&h3b,  g_h3b);
    cudaGetSymbolAddress((void**)&w34,  g_w34);
    cudaGetSymbolAddress((void**)&resh, g_resh);
    cudaGetSymbolAddress((void**)&resl, g_resl);
    cudaGetSymbolAddress((void**)&resz, g_resz);
    cudaGetSymbolAddress((void**)&lst,  g_list);
    cudaGetSymbolAddress((void**)&cnt,  g_count);
    cudaGetSymbolAddress((void**)&rs,   g_rowsum);
    cudaGetSymbolAddress((void**)&rq,   g_rowsq);
    const size_t WSZ = (size_t)HD * HD;

    cudaFuncSetAttribute(gemm_i3<1>,   cudaFuncAttributeMaxDynamicSharedMemorySize, I_SMEM);
    cudaFuncSetAttribute(gemm_i3<0>,   cudaFuncAttributeMaxDynamicSharedMemorySize, I_SMEM);
    cudaFuncSetAttribute(gemm_h3<1,1>, cudaFuncAttributeMaxDynamicSharedMemorySize, R_SMEM);
    cudaFuncSetAttribute(gemm_h3<0,0>, cudaFuncAttributeMaxDynamicSharedMemorySize, R_SMEM);
    cudaFuncSetAttribute(gemm_b1<0,1>, cudaFuncAttributeMaxDynamicSharedMemorySize, D_SMEM);
    cudaFuncSetAttribute(gemm_b1<1,0>, cudaFuncAttributeMaxDynamicSharedMemorySize, D_SMEM);

    const float SXW = (1.f / 127.f) * (0.15f / 127.f);
    const float SHW = (4.f / 127.f) * (0.15f / 127.f);

    // ---- prep ----
    zero_cnt_kernel<<<1, 32>>>();
    qx_kernel<<<(NROWS * HD / 4) / 256, 256>>>((const float4*)x,
        (char4*)xa1, (char4*)xa2, (__half2*)xhi, (__half2*)xlo);
    dim3 tb(32, 32), tg(HD / 32, HD / 32);
    qw_kernel<<<tg, tb>>>(W1, wb1 + 0 * WSZ, wb2 + 0 * WSZ, w12h + 0 * WSZ, w12l + 0 * WSZ);
    qw_kernel<<<tg, tb>>>(W2, wb1 + 1 * WSZ, wb2 + 1 * WSZ, w12h + 1 * WSZ, w12l + 1 * WSZ);
    wt_b<<<tg, tb>>>(W3, w34 + 0 * WSZ);
    wt_b<<<tg, tb>>>(W4, w34 + 1 * WSZ);
    cb_stats_kernel<<<HD, 256>>>(cb, rs, rq);

    // encoder (int8 3-term)
    dim3 gi(HD / 128, NROWS / 128);   // (8, 256)
    gemm_i3<1><<<gi, 256, I_SMEM>>>(xa1, xa2, wb1 + 0*WSZ, wb2 + 0*WSZ, b1, SXW,
                                    nullptr, ha1, ha2);
    gemm_i3<0><<<gi, 256, I_SMEM>>>(ha1, ha2, wb1 + 1*WSZ, wb2 + 1*WSZ, b2, SHW,
                                    z_e, nullptr, nullptr);

    // VQ with certified flagging
    vq2e_kernel<<<NROWS, 256>>>(z_e, cb, rs, rq, z_q, zqh, lst, cnt);

    // rescue (fp16 3-term, count-gated)
    dim3 gg(HD / BN, NROWS / BM);     // (8, 128)
    gemm_h3<1,1><<<gg, THREADS, R_SMEM>>>(xhi, xlo, w12h + 0*WSZ, w12l + 0*WSZ, b1,
                                          nullptr, resh, resl, lst, cnt);
    gemm_h3<0,0><<<gg, THREADS, R_SMEM>>>(resh, resl, w12h + 1*WSZ, w12l + 1*WSZ, b2,
                                          resz, nullptr, nullptr, lst, cnt);
    rescue_dist<<<NROWS, 256>>>(resz, cb, rs, rq, z_q, z_e, zqh, lst, cnt);

    // decoder (1-term bf16)
    gemm_b1<0,1><<<gg, THREADS, D_SMEM>>>(zqh, w34 + 0*WSZ, b3, nullptr, h3b);
    gemm_b1<1,0><<<gg, THREADS, D_SMEM>>>(h3b, w34 + 1*WSZ, b4, x_recon, nullptr);
}

// round 11
// speedup vs baseline: 2.4257x; 2.4257x over previous
#include <cuda_runtime.h>
#include <cuda_bf16.h>
#include <math.h>
#include <stdint.h>

#define NROWS 32768
#define HD    1024

// ---------------------------------------------------------------------------
// Scratch (device globals; no allocations allowed)
// ---------------------------------------------------------------------------
__device__ __nv_bfloat16 g_ahi[(size_t)NROWS * HD];
__device__ __nv_bfloat16 g_alo[(size_t)NROWS * HD];
__device__ __nv_bfloat16 g_bhi[(size_t)NROWS * HD];
__device__ __nv_bfloat16 g_blo[(size_t)NROWS * HD];
__device__ __nv_bfloat16 g_wthi[4][(size_t)HD * HD];
__device__ __nv_bfloat16 g_wtlo[2][(size_t)HD * HD];   // lo only for W1, W2
__device__ float g_rowsum[HD];
__device__ float g_rowsq[HD];

// ---------------------------------------------------------------------------
// PTX helpers (sm_80-era only — harness PTX stage targets plain compute_103)
// ---------------------------------------------------------------------------
__device__ __forceinline__ uint32_t smem_to_u32(const void* p) {
    uint32_t a;
    asm("{ .reg .u64 t; cvta.to.shared.u64 t, %1; cvt.u32.u64 %0, t; }" : "=r"(a) : "l"(p));
    return a;
}
#define CP_ASYNC16(dst, src) \
    asm volatile("cp.async.cg.shared.global [%0], [%1], 16;" :: "r"(dst), "l"(src))
#define CP_COMMIT() asm volatile("cp.async.commit_group;" ::: "memory")
#define CP_WAIT2()  asm volatile("cp.async.wait_group 2;" ::: "memory")
#define CP_WAIT1()  asm volatile("cp.async.wait_group 1;" ::: "memory")
#define CP_WAIT0()  asm volatile("cp.async.wait_group 0;" ::: "memory")

#define LDSM4(r0, r1, r2, r3, addr) \
    asm volatile("ldmatrix.sync.aligned.m8n8.x4.shared.b16 {%0,%1,%2,%3}, [%4];" \
        : "=r"(r0), "=r"(r1), "=r"(r2), "=r"(r3) : "r"(addr))

#define MMA16816(d, a, b) \
    asm volatile("mma.sync.aligned.m16n8k16.row.col.f32.bf16.bf16.f32 " \
        "{%0,%1,%2,%3}, {%4,%5,%6,%7}, {%8,%9}, {%0,%1,%2,%3};" \
        : "+f"((d)[0]), "+f"((d)[1]), "+f"((d)[2]), "+f"((d)[3]) \
        : "r"((a)[0]), "r"((a)[1]), "r"((a)[2]), "r"((a)[3]), \
          "r"((b)[0]), "r"((b)[1]))

__device__ __forceinline__ void split1(float v, __nv_bfloat16& h, __nv_bfloat16& l) {
    h = __float2bfloat16(v);
    l = __float2bfloat16(v - __bfloat162float(h));
}

// ---------------------------------------------------------------------------
// Prep kernels
// ---------------------------------------------------------------------------
__global__ __launch_bounds__(256)
void split_act(const float4* __restrict__ x, __nv_bfloat162* __restrict__ hi,
               __nv_bfloat162* __restrict__ lo)
{
    size_t i = (size_t)blockIdx.x * 256 + threadIdx.x;
    float4 v = x[i];
    __nv_bfloat16 h0,l0,h1,l1,h2,l2,h3,l3;
    split1(v.x,h0,l0); split1(v.y,h1,l1); split1(v.z,h2,l2); split1(v.w,h3,l3);
    __nv_bfloat162 a,b;
    a.x=h0; a.y=h1; b.x=h2; b.y=h3;
    hi[2*i]=a; hi[2*i+1]=b;
    a.x=l0; a.y=l1; b.x=l2; b.y=l3;
    lo[2*i]=a; lo[2*i+1]=b;
}

__global__ __launch_bounds__(1024)
void wsplit_t(const float* __restrict__ W, __nv_bfloat16* __restrict__ hi,
              __nv_bfloat16* __restrict__ lo)
{
    __shared__ float s[32][33];
    int n0 = blockIdx.x * 32, k0 = blockIdx.y * 32;
    s[threadIdx.y][threadIdx.x] = W[(size_t)(k0 + threadIdx.y) * HD + n0 + threadIdx.x];
    __syncthreads();
    float v = s[threadIdx.x][threadIdx.y];
    int n = n0 + threadIdx.y, k = k0 + threadIdx.x;
    __nv_bfloat16 h, l; split1(v, h, l);
    hi[(size_t)n * HD + k] = h;
    lo[(size_t)n * HD + k] = l;
}

__global__ __launch_bounds__(1024)
void wt_hi(const float* __restrict__ W, __nv_bfloat16* __restrict__ hi)
{
    __shared__ float s[32][33];
    int n0 = blockIdx.x * 32, k0 = blockIdx.y * 32;
    s[threadIdx.y][threadIdx.x] = W[(size_t)(k0 + threadIdx.y) * HD + n0 + threadIdx.x];
    __syncthreads();
    float v = s[threadIdx.x][threadIdx.y];
    int n = n0 + threadIdx.y, k = k0 + threadIdx.x;
    hi[(size_t)n * HD + k] = __float2bfloat16(v);
}

__global__ __launch_bounds__(256)
void cb_stats_kernel(const float* __restrict__ cb, float* __restrict__ rowsum,
                     float* __restrict__ rowsq)
{
    const int i = blockIdx.x, tid = threadIdx.x;
    const float* row = cb + (size_t)i * HD;
    float s = 0.f, q = 0.f;
    for (int j = tid; j < HD; j += 256) { float v = row[j]; s += v; q = fmaf(v, v, q); }
    __shared__ float ss[256], qq[256];
    ss[tid] = s; qq[tid] = q;
    __syncthreads();
    for (int off = 128; off > 0; off >>= 1) {
        if (tid < off) { ss[tid] += ss[tid+off]; qq[tid] += qq[tid+off]; }
        __syncthreads();
    }
    if (tid == 0) { rowsum[i] = ss[0]; rowsq[i] = qq[0]; }
}

// ---------------------------------------------------------------------------
// VQ: argmin + gather (fp32 out + plain bf16 for decoder GEMM)
// ---------------------------------------------------------------------------
__global__ __launch_bounds__(256)
void vq_kernel(const float* __restrict__ ze, const float* __restrict__ cb,
               const float* __restrict__ rowsum, const float* __restrict__ rowsq,
               float* __restrict__ zq, __nv_bfloat16* __restrict__ zqh)
{
    const int n = blockIdx.x, tid = threadIdx.x;
    const float* z = ze + (size_t)n * HD;
    float best = INFINITY; int bidx = 0x7fffffff;
    #pragma unroll
    for (int j = 0; j < 4; j++) {
        int i = tid + j * 256;
        float zv = z[i];
        float d = fmaf(1024.0f * zv, zv, fmaf(-2.0f * zv, rowsum[i], rowsq[i]));
        if (d < best || (d == best && i < bidx)) { best = d; bidx = i; }
    }
    __shared__ float sd[256]; __shared__ int si[256];
    sd[tid] = best; si[tid] = bidx;
    __syncthreads();
    for (int off = 128; off > 0; off >>= 1) {
        if (tid < off) {
            float d2 = sd[tid+off]; int i2 = si[tid+off];
            if (d2 < sd[tid] || (d2 == sd[tid] && i2 < si[tid])) { sd[tid]=d2; si[tid]=i2; }
        }
        __syncthreads();
    }
    const int idx = si[0];
    float4 v = reinterpret_cast<const float4*>(cb + (size_t)idx * HD)[tid];
    reinterpret_cast<float4*>(zq + (size_t)n * HD)[tid] = v;
    __nv_bfloat162 a, b;
    a.x = __float2bfloat16(v.x); a.y = __float2bfloat16(v.y);
    b.x = __float2bfloat16(v.z); b.y = __float2bfloat16(v.w);
    __nv_bfloat162* ph = reinterpret_cast<__nv_bfloat162*>(zqh + (size_t)n * HD);
    ph[2*tid] = a; ph[2*tid+1] = b;
}

// ---------------------------------------------------------------------------
// GEMM geometry: CTA 256x128, 256 threads, 8 warps, warp tile 64x64,
// KC=64, cp.async pipeline, 128B-row xor swizzle.
// ---------------------------------------------------------------------------
#define BM 256
#define BN 128
#define KC 64
#define NKI (HD / KC)
#define THREADS 256

// ===== 3-term encoder: C = Ahi*Bhi + Ahi*Blo + Alo*Bhi =====
#define AHI_OFF 0
#define ALO_OFF 32768
#define BHI_OFF 65536
#define BLO_OFF 81920
#define STAGE_B 98304
#define SMEM_TOTAL (2 * STAGE_B)   // 196608

__device__ __forceinline__ void load_stage3(
    uint32_t sdst,
    const __nv_bfloat16* __restrict__ Ahi, const __nv_bfloat16* __restrict__ Alo,
    const __nv_bfloat16* __restrict__ Bhi, const __nv_bfloat16* __restrict__ Blo,
    int mbase, int nbase, int c, int tid)
{
    const int kel = c * KC;
    #pragma unroll
    for (int i = 0; i < 8; ++i) {
        int id = tid + i * THREADS;
        int row = id >> 3, u = id & 7;
        uint32_t so = row * 128 + ((u ^ (row & 7)) << 4);
        CP_ASYNC16(sdst + AHI_OFF + so,
                   (const char*)(Ahi + (size_t)(mbase + row) * HD + kel + u * 8));
        CP_ASYNC16(sdst + ALO_OFF + so,
                   (const char*)(Alo + (size_t)(mbase + row) * HD + kel + u * 8));
    }
    #pragma unroll
    for (int i = 0; i < 4; ++i) {
        int id = tid + i * THREADS;
        int row = id >> 3, u = id & 7;
        uint32_t so = row * 128 + ((u ^ (row & 7)) << 4);
        CP_ASYNC16(sdst + BHI_OFF + so,
                   (const char*)(Bhi + (size_t)(nbase + row) * HD + kel + u * 8));
        CP_ASYNC16(sdst + BLO_OFF + so,
                   (const char*)(Blo + (size_t)(nbase + row) * HD + kel + u * 8));
    }
}

// MODE: 0 = fp32 C; 1 = split bf16 Chi/Clo.
template<int MODE>
__global__ __launch_bounds__(THREADS, 1)
void gemm_mma3(const __nv_bfloat16* __restrict__ Ahi, const __nv_bfloat16* __restrict__ Alo,
               const __nv_bfloat16* __restrict__ Bhi, const __nv_bfloat16* __restrict__ Blo,
               const float* __restrict__ bias,
               float* __restrict__ Cf,
               __nv_bfloat16* __restrict__ Chi, __nv_bfloat16* __restrict__ Clo)
{
    extern __shared__ char smem[];
    const uint32_t sb = smem_to_u32(smem);
    const int tid  = threadIdx.x;
    const int wid  = tid >> 5;
    const int lane = tid & 31;
    const int wm = wid & 3;                 // 4 m-positions x 64
    const int wn = wid >> 2;                // 2 n-positions x 64
    const int mbase = blockIdx.y * BM;
    const int nbase = blockIdx.x * BN;

    float acc[4][8][4];
    #pragma unroll
    for (int i = 0; i < 4; i++)
        #pragma unroll
        for (int j = 0; j < 8; j++)
            #pragma unroll
            for (int k = 0; k < 4; k++) acc[i][j][k] = 0.f;

    const int a_row_l = lane & 15;
    const int a_half  = lane >> 4;
    const int b_n_l   = (lane & 7) + ((lane >> 4) << 3);
    const int b_half  = (lane >> 3) & 1;

    load_stage3(sb, Ahi, Alo, Bhi, Blo, mbase, nbase, 0, tid);
    CP_COMMIT();

    for (int c = 0; c < NKI; ++c) {
        if (c + 1 < NKI) {
            load_stage3(sb + ((c + 1) & 1) * STAGE_B, Ahi, Alo, Bhi, Blo,
                        mbase, nbase, c + 1, tid);
            CP_COMMIT();
            CP_WAIT1();
        } else {
            CP_WAIT0();
        }
        __syncthreads();

        const uint32_t st = sb + (c & 1) * STAGE_B;
        #pragma unroll
        for (int ks = 0; ks < 4; ++ks) {
            uint32_t ah[4][4], bh[8][2], bl[8][2];
            #pragma unroll
            for (int i = 0; i < 4; ++i) {
                int row = wm * 64 + i * 16 + a_row_l;
                int u = ks * 2 + a_half;
                LDSM4(ah[i][0], ah[i][1], ah[i][2], ah[i][3],
                      st + AHI_OFF + row * 128 + ((u ^ (row & 7)) << 4));
            }
            #pragma unroll
            for (int jj = 0; jj < 4; ++jj) {
                int n = wn * 64 + jj * 16 + b_n_l;
                int u = ks * 2 + b_half;
                LDSM4(bh[jj*2][0], bh[jj*2][1], bh[jj*2+1][0], bh[jj*2+1][1],
                      st + BHI_OFF + n * 128 + ((u ^ (n & 7)) << 4));
                LDSM4(bl[jj*2][0], bl[jj*2][1], bl[jj*2+1][0], bl[jj*2+1][1],
                      st + BLO_OFF + n * 128 + ((u ^ (n & 7)) << 4));
            }
            #pragma unroll
            for (int i = 0; i < 4; ++i)
                #pragma unroll
                for (int j = 0; j < 8; ++j) {
                    MMA16816(acc[i][j], ah[i], bh[j]);
                    MMA16816(acc[i][j], ah[i], bl[j]);
                }
            #pragma unroll
            for (int i = 0; i < 4; ++i) {
                int row = wm * 64 + i * 16 + a_row_l;
                int u = ks * 2 + a_half;
                LDSM4(ah[i][0], ah[i][1], ah[i][2], ah[i][3],
                      st + ALO_OFF + row * 128 + ((u ^ (row & 7)) << 4));
            }
            #pragma unroll
            for (int i = 0; i < 4; ++i)
                #pragma unroll
                for (int j = 0; j < 8; ++j)
                    MMA16816(acc[i][j], ah[i], bh[j]);
        }
        __syncthreads();
    }

    #pragma unroll
    for (int j = 0; j < 8; ++j) {
        const int col = nbase + wn * 64 + j * 8 + (lane & 3) * 2;
        const float2 bj = *reinterpret_cast<const float2*>(bias + col);
        #pragma unroll
        for (int i = 0; i < 4; ++i) {
            const int r0 = mbase + wm * 64 + i * 16 + (lane >> 2);
            const int r1 = r0 + 8;
            float v0 = fmaxf(acc[i][j][0] + bj.x, 0.f);
            float v1 = fmaxf(acc[i][j][1] + bj.y, 0.f);
            float v2 = fmaxf(acc[i][j][2] + bj.x, 0.f);
            float v3 = fmaxf(acc[i][j][3] + bj.y, 0.f);
            if (MODE == 0) {
                float2 p0 = {v0, v1}, p1 = {v2, v3};
                *reinterpret_cast<float2*>(Cf + (size_t)r0 * HD + col) = p0;
                *reinterpret_cast<float2*>(Cf + (size_t)r1 * HD + col) = p1;
            } else {
                __nv_bfloat16 h0,l0,h1,l1,h2,l2,h3,l3;
                split1(v0,h0,l0); split1(v1,h1,l1); split1(v2,h2,l2); split1(v3,h3,l3);
                __nv_bfloat162 hh0; hh0.x=h0; hh0.y=h1;
                __nv_bfloat162 ll0; ll0.x=l0; ll0.y=l1;
                __nv_bfloat162 hh1; hh1.x=h2; hh1.y=h3;
                __nv_bfloat162 ll1; ll1.x=l2; ll1.y=l3;
                *reinterpret_cast<__nv_bfloat162*>(Chi + (size_t)r0 * HD + col) = hh0;
                *reinterpret_cast<__nv_bfloat162*>(Clo + (size_t)r0 * HD + col) = ll0;
                *reinterpret_cast<__nv_bfloat162*>(Chi + (size_t)r1 * HD + col) = hh1;
                *reinterpret_cast<__nv_bfloat162*>(Clo + (size_t)r1 * HD + col) = ll1;
            }
        }
    }
}

// ===== 1-term decoder: C = act(A*B + bias) =====
#define A1_OFF 0
#define B1_OFF 32768
#define STAGE1_B 49152
#define SMEM1_TOTAL (3 * STAGE1_B)   // 147456

__device__ __forceinline__ void load_stage1(
    uint32_t sdst,
    const __nv_bfloat16* __restrict__ A, const __nv_bfloat16* __restrict__ B,
    int mbase, int nbase, int c, int tid)
{
    const int kel = c * KC;
    #pragma unroll
    for (int i = 0; i < 8; ++i) {
        int id = tid + i * THREADS;
        int row = id >> 3, u = id & 7;
        CP_ASYNC16(sdst + A1_OFF + row * 128 + ((u ^ (row & 7)) << 4),
                   (const char*)(A + (size_t)(mbase + row) * HD + kel + u * 8));
    }
    #pragma unroll
    for (int i = 0; i < 4; ++i) {
        int id = tid + i * THREADS;
        int row = id >> 3, u = id & 7;
        CP_ASYNC16(sdst + B1_OFF + row * 128 + ((u ^ (row & 7)) << 4),
                   (const char*)(B + (size_t)(nbase + row) * HD + kel + u * 8));
    }
}

// EPI: 0 = relu, 1 = sigmoid.  MODE: 0 = fp32 C; 1 = bf16 Chi only.
template<int EPI, int MODE>
__global__ __launch_bounds__(THREADS, 1)
void gemm_mma1(const __nv_bfloat16* __restrict__ A, const __nv_bfloat16* __restrict__ B,
               const float* __restrict__ bias,
               float* __restrict__ Cf, __nv_bfloat16* __restrict__ Chi)
{
    extern __shared__ char smem[];
    const uint32_t sb = smem_to_u32(smem);
    const int tid  = threadIdx.x;
    const int wid  = tid >> 5;
    const int lane = tid & 31;
    const int wm = wid & 3;
    const int wn = wid >> 2;
    const int mbase = blockIdx.y * BM;
    const int nbase = blockIdx.x * BN;

    float acc[4][8][4];
    #pragma unroll
    for (int i = 0; i < 4; i++)
        #pragma unroll
        for (int j = 0; j < 8; j++)
            #pragma unroll
            for (int k = 0; k < 4; k++) acc[i][j][k] = 0.f;

    const int a_row_l = lane & 15;
    const int a_half  = lane >> 4;
    const int b_n_l   = (lane & 7) + ((lane >> 4) << 3);
    const int b_half  = (lane >> 3) & 1;

    load_stage1(sb + 0 * STAGE1_B, A, B, mbase, nbase, 0, tid);
    CP_COMMIT();
    load_stage1(sb + 1 * STAGE1_B, A, B, mbase, nbase, 1, tid);
    CP_COMMIT();

    int buf = 0;
    for (int c = 0; c < NKI; ++c) {
        if (c + 2 < NKI) {
            int b2 = buf + 2; if (b2 >= 3) b2 -= 3;
            load_stage1(sb + b2 * STAGE1_B, A, B, mbase, nbase, c + 2, tid);
            CP_COMMIT();
            CP_WAIT2();
        } else if (c + 1 < NKI) {
            CP_WAIT1();
        } else {
            CP_WAIT0();
        }
        __syncthreads();

        const uint32_t st = sb + buf * STAGE1_B;
        #pragma unroll
        for (int ks = 0; ks < 4; ++ks) {
            uint32_t ah[4][4], bh[8][2];
            #pragma unroll
            for (int i = 0; i < 4; ++i) {
                int row = wm * 64 + i * 16 + a_row_l;
                int u = ks * 2 + a_half;
                LDSM4(ah[i][0], ah[i][1], ah[i][2], ah[i][3],
                      st + A1_OFF + row * 128 + ((u ^ (row & 7)) << 4));
            }
            #pragma unroll
            for (int jj = 0; jj < 4; ++jj) {
                int n = wn * 64 + jj * 16 + b_n_l;
                int u = ks * 2 + b_half;
                LDSM4(bh[jj*2][0], bh[jj*2][1], bh[jj*2+1][0], bh[jj*2+1][1],
                      st + B1_OFF + n * 128 + ((u ^ (n & 7)) << 4));
            }
            #pragma unroll
            for (int i = 0; i < 4; ++i)
                #pragma unroll
                for (int j = 0; j < 8; ++j)
                    MMA16816(acc[i][j], ah[i], bh[j]);
        }
        __syncthreads();
        buf = buf + 1; if (buf == 3) buf = 0;
    }

    #pragma unroll
    for (int j = 0; j < 8; ++j) {
        const int col = nbase + wn * 64 + j * 8 + (lane & 3) * 2;
        const float2 bj = *reinterpret_cast<const float2*>(bias + col);
        #pragma unroll
        for (int i = 0; i < 4; ++i) {
            const int r0 = mbase + wm * 64 + i * 16 + (lane >> 2);
            const int r1 = r0 + 8;
            float v0 = acc[i][j][0] + bj.x;
            float v1 = acc[i][j][1] + bj.y;
            float v2 = acc[i][j][2] + bj.x;
            float v3 = acc[i][j][3] + bj.y;
            if (EPI == 0) {
                v0 = fmaxf(v0, 0.f); v1 = fmaxf(v1, 0.f);
                v2 = fmaxf(v2, 0.f); v3 = fmaxf(v3, 0.f);
            } else {
                v0 = 1.f / (1.f + expf(-v0)); v1 = 1.f / (1.f + expf(-v1));
                v2 = 1.f / (1.f + expf(-v2)); v3 = 1.f / (1.f + expf(-v3));
            }
            if (MODE == 0) {
                float2 p0 = {v0, v1}, p1 = {v2, v3};
                *reinterpret_cast<float2*>(Cf + (size_t)r0 * HD + col) = p0;
                *reinterpret_cast<float2*>(Cf + (size_t)r1 * HD + col) = p1;
            } else {
                __nv_bfloat162 hh0, hh1;
                hh0.x = __float2bfloat16(v0); hh0.y = __float2bfloat16(v1);
                hh1.x = __float2bfloat16(v2); hh1.y = __float2bfloat16(v3);
                *reinterpret_cast<__nv_bfloat162*>(Chi + (size_t)r0 * HD + col) = hh0;
                *reinterpret_cast<__nv_bfloat162*>(Chi + (size_t)r1 * HD + col) = hh1;
            }
        }
    }
}

// ---------------------------------------------------------------------------
// Launch — order rearranged so ncu's "-s 5 -c 1" capture lands on
// gemm_mma3<1> (launch index 5) instead of a 7us prep kernel.
// cb_stats is only needed before vq_kernel, so it moves after the encoder.
// ---------------------------------------------------------------------------
extern "C" void kernel_launch(void* const* d_in, const int* in_sizes, int n_in,
                              void* d_out, int out_size)
{
    const float* x  = (const float*)d_in[0];
    const float* W1 = (const float*)d_in[1];
    const float* b1 = (const float*)d_in[2];
    const float* W2 = (const float*)d_in[3];
    const float* b2 = (const float*)d_in[4];
    const float* cb = (const float*)d_in[5];
    const float* W3 = (const float*)d_in[6];
    const float* b3 = (const float*)d_in[7];
    const float* W4 = (const float*)d_in[8];
    const float* b4 = (const float*)d_in[9];

    float* out = (float*)d_out;
    float* x_recon = out;
    float* z_e = out + (size_t)NROWS * HD;
    float* z_q = z_e + (size_t)NROWS * HD;

    __nv_bfloat16 *ahi, *alo, *bhi, *blo, *wh, *wl;
    float *rs, *rq;
    cudaGetSymbolAddress((void**)&ahi, g_ahi);
    cudaGetSymbolAddress((void**)&alo, g_alo);
    cudaGetSymbolAddress((void**)&bhi, g_bhi);
    cudaGetSymbolAddress((void**)&blo, g_blo);
    cudaGetSymbolAddress((void**)&wh,  g_wthi);
    cudaGetSymbolAddress((void**)&wl,  g_wtlo);
    cudaGetSymbolAddress((void**)&rs,  g_rowsum);
    cudaGetSymbolAddress((void**)&rq,  g_rowsq);
    const size_t WSZ = (size_t)HD * HD;

    cudaFuncSetAttribute(gemm_mma3<1>,   cudaFuncAttributeMaxDynamicSharedMemorySize, SMEM_TOTAL);
    cudaFuncSetAttribute(gemm_mma3<0>,   cudaFuncAttributeMaxDynamicSharedMemorySize, SMEM_TOTAL);
    cudaFuncSetAttribute(gemm_mma1<0,1>, cudaFuncAttributeMaxDynamicSharedMemorySize, SMEM1_TOTAL);
    cudaFuncSetAttribute(gemm_mma1<1,0>, cudaFuncAttributeMaxDynamicSharedMemorySize, SMEM1_TOTAL);

    dim3 tb(32, 32), tg(HD / 32, HD / 32);
    dim3 gg(HD / BN, NROWS / BM);   // (8, 128)
    dim3 blk(THREADS);

    // launches 0-4: prep
    split_act<<<(NROWS * HD / 4) / 256, 256>>>((const float4*)x,
        (__nv_bfloat162*)ahi, (__nv_bfloat162*)alo);
    wsplit_t<<<tg, tb>>>(W1, wh + 0 * WSZ, wl + 0 * WSZ);
    wsplit_t<<<tg, tb>>>(W2, wh + 1 * WSZ, wl + 1 * WSZ);
    wt_hi  <<<tg, tb>>>(W3, wh + 2 * WSZ);
    wt_hi  <<<tg, tb>>>(W4, wh + 3 * WSZ);

    // launch 5: encoder GEMM1 (ncu -s 5 -c 1 captures THIS)
    gemm_mma3<1><<<gg, blk, SMEM_TOTAL>>>(ahi, alo, wh + 0*WSZ, wl + 0*WSZ, b1,
                                          nullptr, bhi, blo);            // h1 (split)
    gemm_mma3<0><<<gg, blk, SMEM_TOTAL>>>(bhi, blo, wh + 1*WSZ, wl + 1*WSZ, b2,
                                          z_e, nullptr, nullptr);        // z_e fp32

    // codebook stats (needed only before vq)
    cb_stats_kernel<<<HD, 256>>>(cb, rs, rq);

    // VQ (writes z_q fp32 + bf16 into ahi)
    vq_kernel<<<NROWS, 256>>>(z_e, cb, rs, rq, z_q, ahi);

    // decoder (1-term bf16)
    gemm_mma1<0,1><<<gg, blk, SMEM1_TOTAL>>>(ahi, wh + 2*WSZ, b3, nullptr, bhi);
    gemm_mma1<1,0><<<gg, blk, SMEM1_TOTAL>>>(bhi, wh + 3*WSZ, b4, x_recon, nullptr);
}